// round 15
// baseline (speedup 1.0000x reference)
#include <cuda_runtime.h>
#include <cstdint>

#define N0C 1000000
#define N1C 400000
#define N2C 100000
#define PS  52          // padded fp32 row stride
#define E0MAX 2000000
#define E1MAX 500000

typedef unsigned long long ull;

// Scratch device globals (.bss zero-init)
__device__ float g_agg1[(size_t)N1C * PS + 16];   // col 50 accumulates edge count
__device__ float g_h[(size_t)N1C * PS + 16];
__device__ float g_agg2[(size_t)N2C * PS + 16];   // col 50 accumulates edge count
__device__ int   g_rp0[N0C + 16];                 // rowptr (by src) graph 0
__device__ int   g_rp1[N1C + 16];
__device__ int   g_fill0[N0C + 16];
__device__ int   g_fill1[N1C + 16];
__device__ int   g_part0[512];
__device__ int   g_part1[512];
__device__ int   g_part2[512];
__device__ int   g_cdst0[E0MAX + 16];
__device__ int   g_cdst1[E1MAX + 16];
__device__ int   g_flag0[N0C + 16];               // scan workspace list 0
__device__ int   g_flag1[N1C + 16];               // list 1
__device__ int   g_flag2[N1C + 16];               // list 2
__device__ int   g_act0[N0C + 16];                // K1: deg0>0 (sorted)
__device__ int   g_act1[N1C + 16];                // K3: deg1>0 || row<N2C (sorted)
__device__ int   g_act2[N1C + 16];                // K4: deg1>0 (sorted)

// ---------------------------------------------------------------------------
__global__ void zero_all() {
    size_t stride = (size_t)gridDim.x * blockDim.x;
    size_t t0 = (size_t)blockIdx.x * blockDim.x + threadIdx.x;
    float4 z = make_float4(0.f, 0.f, 0.f, 0.f);
    for (size_t i = t0; i < (size_t)N1C * PS / 4; i += stride) ((float4*)g_agg1)[i] = z;
    for (size_t i = t0; i < (size_t)N2C * PS / 4; i += stride) ((float4*)g_agg2)[i] = z;
    for (size_t i = t0; i < (N0C + 16) / 4; i += stride) ((int4*)g_rp0)[i] = make_int4(0,0,0,0);
    for (size_t i = t0; i < (N1C + 16) / 4; i += stride) ((int4*)g_rp1)[i] = make_int4(0,0,0,0);
    for (size_t i = t0; i < (N0C + 16) / 4; i += stride) ((int4*)g_fill0)[i] = make_int4(0,0,0,0);
    for (size_t i = t0; i < (N1C + 16) / 4; i += stride) ((int4*)g_fill1)[i] = make_int4(0,0,0,0);
}

// ---------------------------------------------------------------------------
// CSR build: count -> scan -> ordered act lists (flag/scan/scatter) -> fill
// ---------------------------------------------------------------------------
__global__ void count_edges(const int* __restrict__ src, int* __restrict__ rp, int E) {
    int t = blockIdx.x * 256 + threadIdx.x;
    if (t < E) atomicAdd(&rp[src[t] + 1], 1);
}

__global__ void scan_local(int* __restrict__ a, int* __restrict__ part, int nelem) {
    __shared__ int ts[256];
    int tid = threadIdx.x;
    int base = blockIdx.x * 4096 + tid * 16;
    int v[16]; int s = 0;
#pragma unroll
    for (int i = 0; i < 16; i++) {
        int idx = base + i;
        v[i] = (idx < nelem) ? a[idx] : 0;
        s += v[i];
    }
    ts[tid] = s; __syncthreads();
    for (int off = 1; off < 256; off <<= 1) {
        int t = (tid >= off) ? ts[tid - off] : 0;
        __syncthreads();
        ts[tid] += t;
        __syncthreads();
    }
    int run = (tid > 0) ? ts[tid - 1] : 0;
#pragma unroll
    for (int i = 0; i < 16; i++) {
        run += v[i];
        int idx = base + i;
        if (idx < nelem) a[idx] = run;
    }
    if (tid == 255) part[blockIdx.x] = ts[255];
}

__global__ void scan_part(int* __restrict__ part, int P) {
    __shared__ int s[256];
    int tid = threadIdx.x;
    s[tid] = (tid < P) ? part[tid] : 0; __syncthreads();
    for (int off = 1; off < 256; off <<= 1) {
        int t = (tid >= off) ? s[tid - off] : 0;
        __syncthreads();
        s[tid] += t;
        __syncthreads();
    }
    if (tid < P) part[tid] = s[tid];
}

__global__ void scan_add(int* __restrict__ a, const int* __restrict__ part, int nelem) {
    int blk = blockIdx.x;
    if (blk == 0) return;
    int add = part[blk - 1];
    int base = blk * 4096 + threadIdx.x * 16;
#pragma unroll
    for (int i = 0; i < 16; i++) {
        int idx = base + i;
        if (idx < nelem) a[idx] += add;
    }
}

// flags[i] = (deg(i)>0 || i<n2incl) ? 1 : 0
__global__ void flag_write(const int* __restrict__ rp, int n, int n2incl,
                           int* __restrict__ flags) {
    int i = blockIdx.x * 256 + threadIdx.x;
    if (i < n) flags[i] = ((rp[i + 1] > rp[i]) || (i < n2incl)) ? 1 : 0;
}

// After inclusive scan: act[flags[i]-1] = i  iff flags[i] > flags[i-1].
// Result is SORTED by construction. nact = flags[n-1].
__global__ void scatter_act(const int* __restrict__ flags, int n,
                            int* __restrict__ act) {
    int i = blockIdx.x * 256 + threadIdx.x;
    if (i >= n) return;
    int cur = flags[i];
    int prev = (i > 0) ? flags[i - 1] : 0;
    if (cur > prev) act[cur - 1] = i;
}

__global__ void fill_csr(const int* __restrict__ src, const int* __restrict__ dst,
                         const int* __restrict__ rp, int* __restrict__ fill,
                         int* __restrict__ cdst, int E) {
    int t = blockIdx.x * 256 + threadIdx.x;
    if (t >= E) return;
    int s = src[t];
    int pos = atomicAdd(&fill[s], 1);
    cdst[rp[s] + pos] = dst[t];
}

// ---------------------------------------------------------------------------
// Packed fp32 helpers
// ---------------------------------------------------------------------------
__device__ __forceinline__ void ffma2(ull& d, ull a, ull b) {
    asm("fma.rn.f32x2 %0, %1, %2, %0;" : "+l"(d) : "l"(a), "l"(b));
}
__device__ __forceinline__ ull bcast2(float x) {
    ull r;
    asm("mov.b64 %0, {%1, %1};" : "=l"(r) : "r"(__float_as_uint(x)));
    return r;
}
__device__ __forceinline__ uint32_t smem_u32(const void* p) {
    uint32_t a;
    asm("{ .reg .u64 t; cvta.to.shared.u64 t, %1; cvt.u32.u64 %0, t; }" : "=r"(a) : "l"(p));
    return a;
}
__device__ __forceinline__ void redv4(float* p, float2 a, float2 b) {
    asm volatile("red.global.add.v4.f32 [%0], {%1, %2, %3, %4};"
                 :: "l"(p), "f"(a.x), "f"(a.y), "f"(b.x), "f"(b.y) : "memory");
}
__device__ __forceinline__ void redv2(float* p, float2 a) {
    asm volatile("red.global.add.v2.f32 [%0], {%1, %2};"
                 :: "l"(p), "f"(a.x), "f"(a.y) : "memory");
}
union F4U { float4 f; ull u[2]; };
union F2U { float2 f; ull u; };

// FMA micro-block: acc[2][13] += a{0,1} * W-row(26 cols)
__device__ __forceinline__ void fma_block(ull acc[2][13], float a0f, float a1f,
                                          const float* wk)
{
    ull av0 = bcast2(a0f);
    ull av1 = bcast2(a1f);
    F4U w0, w1, w2; F2U w3;
    w0.f = *(const float4*)(wk);
    w1.f = *(const float4*)(wk + 4);
    w2.f = *(const float4*)(wk + 8);
    w3.f = *(const float2*)(wk + 12);
    ffma2(acc[0][0], av0, w0.u[0]); ffma2(acc[1][0], av1, w0.u[0]);
    ffma2(acc[0][1], av0, w0.u[1]); ffma2(acc[1][1], av1, w0.u[1]);
    ffma2(acc[0][2], av0, w1.u[0]); ffma2(acc[1][2], av1, w1.u[0]);
    ffma2(acc[0][3], av0, w1.u[1]); ffma2(acc[1][3], av1, w1.u[1]);
    ffma2(acc[0][4], av0, w2.u[0]); ffma2(acc[1][4], av1, w2.u[0]);
    ffma2(acc[0][5], av0, w2.u[1]); ffma2(acc[1][5], av1, w2.u[1]);
    ffma2(acc[0][6], av0, w3.u);    ffma2(acc[1][6], av1, w3.u);
    F4U y0, y1, y2;
    y0.f = *(const float4*)(wk + 14);
    y1.f = *(const float4*)(wk + 18);
    y2.f = *(const float4*)(wk + 22);
    ffma2(acc[0][7],  av0, y0.u[0]); ffma2(acc[1][7],  av1, y0.u[0]);
    ffma2(acc[0][8],  av0, y0.u[1]); ffma2(acc[1][8],  av1, y0.u[1]);
    ffma2(acc[0][9],  av0, y1.u[0]); ffma2(acc[1][9],  av1, y1.u[0]);
    ffma2(acc[0][10], av0, y1.u[1]); ffma2(acc[1][10], av1, y1.u[1]);
    ffma2(acc[0][11], av0, y2.u[0]); ffma2(acc[1][11], av1, y2.u[0]);
    ffma2(acc[0][12], av0, y2.u[1]); ffma2(acc[1][12], av1, y2.u[1]);
}

// Fused scatter epilogue for one row (by real row id).
__device__ __forceinline__ void scat_row(float2 c[13], int row, int sub,
                                         const int* __restrict__ rp,
                                         const int* __restrict__ cdst,
                                         float* __restrict__ agg)
{
    if (sub == 1) { c[12].x = 1.0f; c[12].y = 0.0f; }
    int beg = rp[row], end = rp[row + 1];
    for (int e = beg; e < end; e++) {
        int d = __ldg(&cdst[e]);
        float* p = agg + (size_t)d * PS + sub * 26;
        if (sub == 0) {
            redv4(p,      c[0],  c[1]);
            redv4(p + 4,  c[2],  c[3]);
            redv4(p + 8,  c[4],  c[5]);
            redv4(p + 12, c[6],  c[7]);
            redv4(p + 16, c[8],  c[9]);
            redv4(p + 20, c[10], c[11]);
            redv2(p + 24, c[12]);
        } else {
            redv2(p,      c[0]);
            redv4(p + 2,  c[1],  c[2]);
            redv4(p + 6,  c[3],  c[4]);
            redv4(p + 10, c[5],  c[6]);
            redv4(p + 14, c[7],  c[8]);
            redv4(p + 18, c[9],  c[10]);
            redv4(p + 22, c[11], c[12]);
        }
    }
}

// ---------------------------------------------------------------------------
// Staged GEMM (D=128) over SORTED active-row list. SCAT: red into agg via CSR.
// else: store out (+ AGG mean/bias via col-50 count, + RELU).
// ---------------------------------------------------------------------------
#define WS_F   0
#define BS_F   7168
#define ACT_F  7224
#define AS0_F  7488
#define AS1_F  16704
#define SMEM_STAGED_BYTES (25920 * 4)

template <bool SCAT, bool AGG, bool RELU>
__global__ void __launch_bounds__(256, 2)
gemm128st(const float* __restrict__ A, const float* __restrict__ W,
          const float* __restrict__ bias, const float* __restrict__ aggin,
          const int* __restrict__ rp, const int* __restrict__ cdst,
          const int* __restrict__ act, const int* __restrict__ nactp,
          float* __restrict__ out)
{
    const int nact = __ldg(nactp);
    const int rowbase_blk = blockIdx.x * 256;
    if (rowbase_blk >= nact) return;

    extern __shared__ float sm[];
    float* Ws = sm + WS_F;
    float* Bs = sm + BS_F;
    int* acts = (int*)(sm + ACT_F);
    const uint32_t smb = smem_u32(sm);

    const int tid = threadIdx.x;

    {
        int gi = rowbase_blk + tid;
        acts[tid] = __ldg(&act[(gi < nact) ? gi : (nact - 1)]);
    }
    for (int i = tid; i < 7168; i += 256) Ws[i] = 0.f;
    if (tid < 56) Bs[tid] = 0.f;
    __syncthreads();
    for (int i = tid; i < 128 * 50; i += 256) {
        int k = i / 50, c = i % 50;
        Ws[k * 56 + ((c < 26) ? c : c + 2)] = W[i];
    }
    if (AGG && tid < 50) Bs[(tid < 26) ? tid : tid + 2] = bias[tid];

#pragma unroll
    for (int j = 0; j < 8; j++) {
        int idx = j * 256 + tid;
        int row = idx >> 3, f4 = idx & 7;
        const float* g = A + (size_t)acts[row] * 128 + f4 * 4;
        uint32_t s = smb + (AS0_F + row * 36 + f4 * 4) * 4;
        asm volatile("cp.async.cg.shared.global [%0], [%1], 16;" :: "r"(s), "l"(g));
    }
    asm volatile("cp.async.commit_group;");
    asm volatile("cp.async.wait_group 0;");
    __syncthreads();

    const int warp = tid >> 5, lane = tid & 31;
    const int sub = lane & 1, rid = lane >> 1;
    const int lrow0 = warp * 32 + rid;

    ull acc[2][13];
#pragma unroll
    for (int r = 0; r < 2; r++)
#pragma unroll
        for (int j = 0; j < 13; j++) acc[r][j] = 0ULL;

    int cur = 0;
#pragma unroll 1
    for (int p = 0; p < 4; p++) {
        if (p < 3) {
            uint32_t dstb = smb + ((cur ? AS0_F : AS1_F)) * 4;
#pragma unroll
            for (int j = 0; j < 8; j++) {
                int idx = j * 256 + tid;
                int row = idx >> 3, f4 = idx & 7;
                const float* g = A + (size_t)acts[row] * 128 + (p + 1) * 32 + f4 * 4;
                uint32_t s = dstb + (row * 36 + f4 * 4) * 4;
                asm volatile("cp.async.cg.shared.global [%0], [%1], 16;" :: "r"(s), "l"(g));
            }
            asm volatile("cp.async.commit_group;");
        }

        const float* Asc = sm + (cur ? AS1_F : AS0_F);
        const float* a0p = Asc + lrow0 * 36;
        const float* a1p = Asc + (lrow0 + 16) * 36;
        const float* wb = Ws + (p * 32) * 56 + sub * 28;
#pragma unroll
        for (int k0 = 0; k0 < 32; k0 += 4) {
            float4 a0 = *(const float4*)(a0p + k0);
            float4 a1 = *(const float4*)(a1p + k0);
            fma_block(acc, a0.x, a1.x, wb + (k0 + 0) * 56);
            fma_block(acc, a0.y, a1.y, wb + (k0 + 1) * 56);
            fma_block(acc, a0.z, a1.z, wb + (k0 + 2) * 56);
            fma_block(acc, a0.w, a1.w, wb + (k0 + 3) * 56);
        }

        asm volatile("cp.async.wait_group 0;");
        __syncthreads();
        cur ^= 1;
    }

#pragma unroll
    for (int r = 0; r < 2; r++) {
        int lidx = lrow0 + 16 * r;
        if (rowbase_blk + lidx >= nact) continue;
        int row = acts[lidx];
        float2 c[13];
#pragma unroll
        for (int j = 0; j < 13; j++) { F2U cv; cv.u = acc[r][j]; c[j] = cv.f; }
        if (SCAT) {
            scat_row(c, row, sub, rp, cdst, out);
        } else {
            if (AGG) {
                const float* ag = aggin + (size_t)row * PS;
                float ic = 1.f / fmaxf(ag[50], 1.f);
                const float* agh = ag + sub * 26;
                const float* bs = Bs + sub * 28;
#pragma unroll
                for (int j = 0; j < 13; j++) {
                    float2 g = *(const float2*)(agh + 2 * j);
                    c[j].x += g.x * ic + bs[2 * j];
                    c[j].y += g.y * ic + bs[2 * j + 1];
                }
            }
            if (RELU) {
#pragma unroll
                for (int j = 0; j < 13; j++) {
                    c[j].x = fmaxf(c[j].x, 0.f);
                    c[j].y = fmaxf(c[j].y, 0.f);
                }
            }
            float* op = out + (size_t)row * PS + sub * 26;
#pragma unroll
            for (int j = 0; j < 13; j++) *(float2*)(op + 2 * j) = c[j];
        }
    }
}

// ---------------------------------------------------------------------------
// Small-D GEMM (D=52, direct LDG). Act list when SCAT; FINAL: dot Wo + relu.
// ---------------------------------------------------------------------------
template <bool SCAT, bool AGG, bool FINAL>
__global__ void __launch_bounds__(256, 2)
gemm52(const float* __restrict__ A, const float* __restrict__ W,
       const float* __restrict__ bias, const float* __restrict__ aggin,
       const int* __restrict__ rp, const int* __restrict__ cdst,
       const int* __restrict__ act, const int* __restrict__ nactp,
       float* __restrict__ out, int nrows,
       const float* __restrict__ Wo, const float* __restrict__ bo)
{
    const int nact = SCAT ? __ldg(nactp) : nrows;
    const int rowbase_blk = blockIdx.x * 256;
    if (rowbase_blk >= nact) return;

    __shared__ float Ws[52 * 56];
    __shared__ float Bs[56];
    __shared__ float Wos[56];
    __shared__ int acts[256];

    const int tid = threadIdx.x;
    if (SCAT) {
        int gi = rowbase_blk + tid;
        acts[tid] = __ldg(&act[(gi < nact) ? gi : (nact - 1)]);
    }
    for (int i = tid; i < 52 * 56; i += 256) Ws[i] = 0.f;
    if (tid < 56) { Bs[tid] = 0.f; Wos[tid] = 0.f; }
    __syncthreads();
    for (int i = tid; i < 50 * 50; i += 256) {
        int k = i / 50, c = i % 50;
        Ws[k * 56 + ((c < 26) ? c : c + 2)] = W[i];
    }
    if (AGG && tid < 50) Bs[(tid < 26) ? tid : tid + 2] = bias[tid];
    if (FINAL && tid < 50) Wos[(tid < 26) ? tid : tid + 2] = Wo[tid];
    __syncthreads();

    const int warp = tid >> 5, lane = tid & 31;
    const int sub = lane & 1, rid = lane >> 1;
    const int lrow0 = warp * 32 + rid;

    int realrow[2];
    const float* Ar[2];
#pragma unroll
    for (int r = 0; r < 2; r++) {
        int lidx = lrow0 + 16 * r;
        int gidx = rowbase_blk + lidx;
        bool v = gidx < nact;
        realrow[r] = SCAT ? acts[lidx] : (v ? gidx : 0);
        Ar[r] = A + (size_t)(v ? realrow[r] : 0) * PS;
    }

    ull acc[2][13];
#pragma unroll
    for (int r = 0; r < 2; r++)
#pragma unroll
        for (int j = 0; j < 13; j++) acc[r][j] = 0ULL;

    float4 cur0 = *(const float4*)(Ar[0]);
    float4 cur1 = *(const float4*)(Ar[1]);
#pragma unroll 1
    for (int k0 = 0; k0 < 52; k0 += 4) {
        const int kn = (k0 + 4 < 52) ? k0 + 4 : 0;
        float4 nxt0 = *(const float4*)(Ar[0] + kn);
        float4 nxt1 = *(const float4*)(Ar[1] + kn);
        const float* wb = Ws + k0 * 56 + sub * 28;
        fma_block(acc, cur0.x, cur1.x, wb);
        fma_block(acc, cur0.y, cur1.y, wb + 56);
        fma_block(acc, cur0.z, cur1.z, wb + 112);
        fma_block(acc, cur0.w, cur1.w, wb + 168);
        cur0 = nxt0; cur1 = nxt1;
    }

#pragma unroll
    for (int r = 0; r < 2; r++) {
        int lidx = lrow0 + 16 * r;
        if (rowbase_blk + lidx >= nact) continue;
        int row = realrow[r];
        float2 c[13];
#pragma unroll
        for (int j = 0; j < 13; j++) { F2U cv; cv.u = acc[r][j]; c[j] = cv.f; }
        if (SCAT) {
            scat_row(c, row, sub, rp, cdst, out);
        } else {
            if (AGG) {
                const float* ag = aggin + (size_t)row * PS;
                float ic = 1.f / fmaxf(ag[50], 1.f);
                const float* agh = ag + sub * 26;
                const float* bs = Bs + sub * 28;
#pragma unroll
                for (int j = 0; j < 13; j++) {
                    float2 g = *(const float2*)(agh + 2 * j);
                    c[j].x += g.x * ic + bs[2 * j];
                    c[j].y += g.y * ic + bs[2 * j + 1];
                }
            }
            if (FINAL) {
                const float* ws = Wos + sub * 28;
                float p = 0.f;
#pragma unroll
                for (int j = 0; j < 13; j++)
                    p += c[j].x * ws[2 * j] + c[j].y * ws[2 * j + 1];
                p += __shfl_xor_sync(0xffffffffu, p, 1);
                if (sub == 0) out[row] = fmaxf(p + bo[0], 0.f);
            } else {
                float* op = out + (size_t)row * PS + sub * 26;
#pragma unroll
                for (int j = 0; j < 13; j++) *(float2*)(op + 2 * j) = c[j];
            }
        }
    }
}

// ---------------------------------------------------------------------------
extern "C" void kernel_launch(void* const* d_in, const int* in_sizes, int n_in,
                              void* d_out, int out_size)
{
    const float* x    = (const float*)d_in[0];
    const int*   src0 = (const int*)d_in[2];
    const int*   dst0 = (const int*)d_in[3];
    const int*   src1 = (const int*)d_in[4];
    const int*   dst1 = (const int*)d_in[5];
    const float* Wl1  = (const float*)d_in[8];
    const float* bl1  = (const float*)d_in[9];
    const float* Wr1  = (const float*)d_in[10];
    const float* Wl2  = (const float*)d_in[11];
    const float* bl2  = (const float*)d_in[12];
    const float* Wr2  = (const float*)d_in[13];
    const float* Wo   = (const float*)d_in[14];
    const float* bo   = (const float*)d_in[15];
    float* out = (float*)d_out;

    const int N0 = in_sizes[0] / 128;
    const int E0 = in_sizes[2];
    const int E1 = in_sizes[4];

    float *p_agg1, *p_h, *p_agg2;
    int *p_rp0, *p_rp1, *p_f0, *p_f1, *p_pt0, *p_pt1, *p_pt2, *p_cd0, *p_cd1;
    int *p_fl0, *p_fl1, *p_fl2, *p_a0, *p_a1, *p_a2;
    cudaGetSymbolAddress((void**)&p_agg1, g_agg1);
    cudaGetSymbolAddress((void**)&p_h,    g_h);
    cudaGetSymbolAddress((void**)&p_agg2, g_agg2);
    cudaGetSymbolAddress((void**)&p_rp0,  g_rp0);
    cudaGetSymbolAddress((void**)&p_rp1,  g_rp1);
    cudaGetSymbolAddress((void**)&p_f0,   g_fill0);
    cudaGetSymbolAddress((void**)&p_f1,   g_fill1);
    cudaGetSymbolAddress((void**)&p_pt0,  g_part0);
    cudaGetSymbolAddress((void**)&p_pt1,  g_part1);
    cudaGetSymbolAddress((void**)&p_pt2,  g_part2);
    cudaGetSymbolAddress((void**)&p_cd0,  g_cdst0);
    cudaGetSymbolAddress((void**)&p_cd1,  g_cdst1);
    cudaGetSymbolAddress((void**)&p_fl0,  g_flag0);
    cudaGetSymbolAddress((void**)&p_fl1,  g_flag1);
    cudaGetSymbolAddress((void**)&p_fl2,  g_flag2);
    cudaGetSymbolAddress((void**)&p_a0,   g_act0);
    cudaGetSymbolAddress((void**)&p_a1,   g_act1);
    cudaGetSymbolAddress((void**)&p_a2,   g_act2);

    cudaFuncSetAttribute(gemm128st<true, false, false>,
                         cudaFuncAttributeMaxDynamicSharedMemorySize, SMEM_STAGED_BYTES);
    cudaFuncSetAttribute(gemm128st<false, true, true>,
                         cudaFuncAttributeMaxDynamicSharedMemorySize, SMEM_STAGED_BYTES);

    const int n0e = N0 + 1;
    const int n1e = N1C + 1;
    const int nb0 = (n0e + 4095) / 4096;
    const int nb1 = (n1e + 4095) / 4096;
    const int nf0 = (N0 + 4095) / 4096;
    const int nf1 = (N1C + 4095) / 4096;

    // 0) zero accumulators + CSR arrays
    zero_all<<<2048, 256>>>();

    // 1) rowptr scans
    count_edges<<<(E0 + 255) / 256, 256>>>(src0, p_rp0, E0);
    count_edges<<<(E1 + 255) / 256, 256>>>(src1, p_rp1, E1);
    scan_local<<<nb0, 256>>>(p_rp0, p_pt0, n0e);
    scan_local<<<nb1, 256>>>(p_rp1, p_pt1, n1e);
    scan_part<<<1, 256>>>(p_pt0, nb0);
    scan_part<<<1, 256>>>(p_pt1, nb1);
    scan_add<<<nb0, 256>>>(p_rp0, p_pt0, n0e);
    scan_add<<<nb1, 256>>>(p_rp1, p_pt1, n1e);

    // 2) sorted active-row lists via flag -> scan -> scatter
    flag_write<<<(N0 + 255) / 256, 256>>>(p_rp0, N0, 0, p_fl0);
    flag_write<<<(N1C + 255) / 256, 256>>>(p_rp1, N1C, N2C, p_fl1);
    flag_write<<<(N1C + 255) / 256, 256>>>(p_rp1, N1C, 0, p_fl2);
    scan_local<<<nf0, 256>>>(p_fl0, p_pt0, N0);
    scan_local<<<nf1, 256>>>(p_fl1, p_pt1, N1C);
    scan_local<<<nf1, 256>>>(p_fl2, p_pt2, N1C);
    scan_part<<<1, 256>>>(p_pt0, nf0);
    scan_part<<<1, 256>>>(p_pt1, nf1);
    scan_part<<<1, 256>>>(p_pt2, nf1);
    scan_add<<<nf0, 256>>>(p_fl0, p_pt0, N0);
    scan_add<<<nf1, 256>>>(p_fl1, p_pt1, N1C);
    scan_add<<<nf1, 256>>>(p_fl2, p_pt2, N1C);
    scatter_act<<<(N0 + 255) / 256, 256>>>(p_fl0, N0, p_a0);
    scatter_act<<<(N1C + 255) / 256, 256>>>(p_fl1, N1C, p_a1);
    scatter_act<<<(N1C + 255) / 256, 256>>>(p_fl2, N1C, p_a2);

    // 3) CSR adjacency fill
    fill_csr<<<(E0 + 255) / 256, 256>>>(src0, dst0, p_rp0, p_f0, p_cd0, E0);
    fill_csr<<<(E1 + 255) / 256, 256>>>(src1, dst1, p_rp1, p_f1, p_cd1, E1);

    // 4) agg1 <- scatter-sum over edges0 of (x @ Wl1), active src rows only
    gemm128st<true, false, false><<<(N0 + 255) / 256, 256, SMEM_STAGED_BYTES>>>(
        x, Wl1, nullptr, nullptr, p_rp0, p_cd0, p_a0, p_fl0 + N0 - 1, p_agg1);

    // 5) h = relu(x@Wr1 + bl1 + agg1/cnt) for rows used downstream
    gemm128st<false, true, true><<<(N1C + 255) / 256, 256, SMEM_STAGED_BYTES>>>(
        x, Wr1, bl1, p_agg1, nullptr, nullptr, p_a1, p_fl1 + N1C - 1, p_h);

    // 6) agg2 <- scatter-sum over edges1 of (h @ Wl2), active src rows only
    gemm52<true, false, false><<<(N1C + 255) / 256, 256>>>(
        p_h, Wl2, nullptr, nullptr, p_rp1, p_cd1, p_a2, p_fl2 + N1C - 1, p_agg2,
        N1C, nullptr, nullptr);

    // 7) out = relu((h[:n2]@Wr2 + bl2 + agg2/cnt) @ Wo + bo)   [n2, 1]
    gemm52<false, true, true><<<(N2C + 255) / 256, 256>>>(
        p_h, Wr2, bl2, p_agg2, nullptr, nullptr, nullptr, nullptr, out,
        N2C, Wo, bo);
}

// round 16
// speedup vs baseline: 1.0382x; 1.0382x over previous
#include <cuda_runtime.h>
#include <cstdint>

#define N0C 1000000
#define N1C 400000
#define N2C 100000
#define PS  52          // padded fp32 row stride
#define E0MAX 2000000
#define E1MAX 500000

typedef unsigned long long ull;

// Scratch device globals (.bss zero-init)
__device__ float g_agg1[(size_t)N1C * PS + 16];   // col 50 accumulates edge count
__device__ float g_h[(size_t)N1C * PS + 16];
__device__ float g_agg2[(size_t)N2C * PS + 16];   // col 50 accumulates edge count
__device__ int   g_rp0[N0C + 16];                 // rowptr (by src) graph 0
__device__ int   g_rp1[N1C + 16];
__device__ int   g_fill0[N0C + 16];
__device__ int   g_fill1[N1C + 16];
__device__ int   g_part0[512];
__device__ int   g_part1[512];
__device__ int   g_cdst0[E0MAX + 16];
__device__ int   g_cdst1[E1MAX + 16];

// ---------------------------------------------------------------------------
__global__ void zero_all() {
    size_t stride = (size_t)gridDim.x * blockDim.x;
    size_t t0 = (size_t)blockIdx.x * blockDim.x + threadIdx.x;
    float4 z = make_float4(0.f, 0.f, 0.f, 0.f);
    for (size_t i = t0; i < (size_t)N1C * PS / 4; i += stride) ((float4*)g_agg1)[i] = z;
    for (size_t i = t0; i < (size_t)N2C * PS / 4; i += stride) ((float4*)g_agg2)[i] = z;
    for (size_t i = t0; i < (N0C + 16) / 4; i += stride) ((int4*)g_rp0)[i] = make_int4(0,0,0,0);
    for (size_t i = t0; i < (N1C + 16) / 4; i += stride) ((int4*)g_rp1)[i] = make_int4(0,0,0,0);
    for (size_t i = t0; i < (N0C + 16) / 4; i += stride) ((int4*)g_fill0)[i] = make_int4(0,0,0,0);
    for (size_t i = t0; i < (N1C + 16) / 4; i += stride) ((int4*)g_fill1)[i] = make_int4(0,0,0,0);
}

// ---------------------------------------------------------------------------
// CSR build (merged: both graphs per launch): count -> scan(3) -> fill
// ---------------------------------------------------------------------------
__global__ void count_edges2(const int* __restrict__ s0, int E0,
                             const int* __restrict__ s1, int E1) {
    int t = blockIdx.x * 256 + threadIdx.x;
    if (t < E0) atomicAdd(&g_rp0[s0[t] + 1], 1);
    if (t < E1) atomicAdd(&g_rp1[s1[t] + 1], 1);
}

__device__ __forceinline__ void scan_local_body(int* __restrict__ a,
                                                int* __restrict__ part,
                                                int nelem, int blk) {
    __shared__ int ts[256];
    int tid = threadIdx.x;
    int base = blk * 4096 + tid * 16;
    int v[16]; int s = 0;
#pragma unroll
    for (int i = 0; i < 16; i++) {
        int idx = base + i;
        v[i] = (idx < nelem) ? a[idx] : 0;
        s += v[i];
    }
    ts[tid] = s; __syncthreads();
    for (int off = 1; off < 256; off <<= 1) {
        int t = (tid >= off) ? ts[tid - off] : 0;
        __syncthreads();
        ts[tid] += t;
        __syncthreads();
    }
    int run = (tid > 0) ? ts[tid - 1] : 0;
#pragma unroll
    for (int i = 0; i < 16; i++) {
        run += v[i];
        int idx = base + i;
        if (idx < nelem) a[idx] = run;
    }
    if (tid == 255) part[blk] = ts[255];
}

__global__ void scan_local2(int* __restrict__ a0, int* __restrict__ p0, int n0,
                            int nb0, int* __restrict__ a1, int* __restrict__ p1,
                            int n1) {
    int blk = blockIdx.x;
    if (blk < nb0) scan_local_body(a0, p0, n0, blk);
    else           scan_local_body(a1, p1, n1, blk - nb0);
}

__device__ __forceinline__ void scan_part_body(int* __restrict__ part, int P) {
    __shared__ int s[256];
    int tid = threadIdx.x;
    s[tid] = (tid < P) ? part[tid] : 0; __syncthreads();
    for (int off = 1; off < 256; off <<= 1) {
        int t = (tid >= off) ? s[tid - off] : 0;
        __syncthreads();
        s[tid] += t;
        __syncthreads();
    }
    if (tid < P) part[tid] = s[tid];
}

__global__ void scan_part2(int* __restrict__ p0, int P0,
                           int* __restrict__ p1, int P1) {
    if (blockIdx.x == 0) scan_part_body(p0, P0);
    else                 scan_part_body(p1, P1);
}

__global__ void scan_add2(int* __restrict__ a0, const int* __restrict__ p0,
                          int n0, int nb0, int* __restrict__ a1,
                          const int* __restrict__ p1, int n1) {
    int blk = blockIdx.x;
    int* a; const int* p; int nelem; int lb;
    if (blk < nb0) { a = a0; p = p0; nelem = n0; lb = blk; }
    else           { a = a1; p = p1; nelem = n1; lb = blk - nb0; }
    if (lb == 0) return;
    int add = p[lb - 1];
    int base = lb * 4096 + threadIdx.x * 16;
#pragma unroll
    for (int i = 0; i < 16; i++) {
        int idx = base + i;
        if (idx < nelem) a[idx] += add;
    }
}

__global__ void fill_csr2(const int* __restrict__ s0, const int* __restrict__ d0,
                          int E0, const int* __restrict__ s1,
                          const int* __restrict__ d1, int E1) {
    int t = blockIdx.x * 256 + threadIdx.x;
    if (t < E0) {
        int s = s0[t];
        int pos = atomicAdd(&g_fill0[s], 1);
        g_cdst0[g_rp0[s] + pos] = d0[t];
    }
    if (t < E1) {
        int s = s1[t];
        int pos = atomicAdd(&g_fill1[s], 1);
        g_cdst1[g_rp1[s] + pos] = d1[t];
    }
}

// ---------------------------------------------------------------------------
// Packed fp32 helpers
// ---------------------------------------------------------------------------
__device__ __forceinline__ void ffma2(ull& d, ull a, ull b) {
    asm("fma.rn.f32x2 %0, %1, %2, %0;" : "+l"(d) : "l"(a), "l"(b));
}
__device__ __forceinline__ ull bcast2(float x) {
    ull r;
    asm("mov.b64 %0, {%1, %1};" : "=l"(r) : "r"(__float_as_uint(x)));
    return r;
}
__device__ __forceinline__ uint32_t smem_u32(const void* p) {
    uint32_t a;
    asm("{ .reg .u64 t; cvta.to.shared.u64 t, %1; cvt.u32.u64 %0, t; }" : "=r"(a) : "l"(p));
    return a;
}
// cp.async 16B with L2 evict-first policy (streaming source, protect agg in L2)
__device__ __forceinline__ void cp16_ef(uint32_t s, const float* g) {
    asm volatile(
        "{\n\t.reg .b64 ph;\n\t"
        "createpolicy.fractional.L2::evict_first.b64 ph, 1.0;\n\t"
        "cp.async.cg.shared.global.L2::cache_hint [%0], [%1], 16, ph;\n\t}"
        :: "r"(s), "l"(g));
}
__device__ __forceinline__ void redv4(float* p, float2 a, float2 b) {
    asm volatile("red.global.add.v4.f32 [%0], {%1, %2, %3, %4};"
                 :: "l"(p), "f"(a.x), "f"(a.y), "f"(b.x), "f"(b.y) : "memory");
}
__device__ __forceinline__ void redv2(float* p, float2 a) {
    asm volatile("red.global.add.v2.f32 [%0], {%1, %2};"
                 :: "l"(p), "f"(a.x), "f"(a.y) : "memory");
}
union F4U { float4 f; ull u[2]; };
union F2U { float2 f; ull u; };

// FMA micro-block: acc[2][13] += a{0,1} * W-row(26 cols)
__device__ __forceinline__ void fma_block(ull acc[2][13], float a0f, float a1f,
                                          const float* wk)
{
    ull av0 = bcast2(a0f);
    ull av1 = bcast2(a1f);
    F4U w0, w1, w2; F2U w3;
    w0.f = *(const float4*)(wk);
    w1.f = *(const float4*)(wk + 4);
    w2.f = *(const float4*)(wk + 8);
    w3.f = *(const float2*)(wk + 12);
    ffma2(acc[0][0], av0, w0.u[0]); ffma2(acc[1][0], av1, w0.u[0]);
    ffma2(acc[0][1], av0, w0.u[1]); ffma2(acc[1][1], av1, w0.u[1]);
    ffma2(acc[0][2], av0, w1.u[0]); ffma2(acc[1][2], av1, w1.u[0]);
    ffma2(acc[0][3], av0, w1.u[1]); ffma2(acc[1][3], av1, w1.u[1]);
    ffma2(acc[0][4], av0, w2.u[0]); ffma2(acc[1][4], av1, w2.u[0]);
    ffma2(acc[0][5], av0, w2.u[1]); ffma2(acc[1][5], av1, w2.u[1]);
    ffma2(acc[0][6], av0, w3.u);    ffma2(acc[1][6], av1, w3.u);
    F4U y0, y1, y2;
    y0.f = *(const float4*)(wk + 14);
    y1.f = *(const float4*)(wk + 18);
    y2.f = *(const float4*)(wk + 22);
    ffma2(acc[0][7],  av0, y0.u[0]); ffma2(acc[1][7],  av1, y0.u[0]);
    ffma2(acc[0][8],  av0, y0.u[1]); ffma2(acc[1][8],  av1, y0.u[1]);
    ffma2(acc[0][9],  av0, y1.u[0]); ffma2(acc[1][9],  av1, y1.u[0]);
    ffma2(acc[0][10], av0, y1.u[1]); ffma2(acc[1][10], av1, y1.u[1]);
    ffma2(acc[0][11], av0, y2.u[0]); ffma2(acc[1][11], av1, y2.u[0]);
    ffma2(acc[0][12], av0, y2.u[1]); ffma2(acc[1][12], av1, y2.u[1]);
}

// Fused scatter epilogue for one row (by real row id).
__device__ __forceinline__ void scat_row(float2 c[13], int row, int sub,
                                         const int* __restrict__ rp,
                                         const int* __restrict__ cdst,
                                         float* __restrict__ agg)
{
    if (sub == 1) { c[12].x = 1.0f; c[12].y = 0.0f; }
    int beg = rp[row], end = rp[row + 1];
    for (int e = beg; e < end; e++) {
        int d = __ldg(&cdst[e]);
        float* p = agg + (size_t)d * PS + sub * 26;
        if (sub == 0) {
            redv4(p,      c[0],  c[1]);
            redv4(p + 4,  c[2],  c[3]);
            redv4(p + 8,  c[4],  c[5]);
            redv4(p + 12, c[6],  c[7]);
            redv4(p + 16, c[8],  c[9]);
            redv4(p + 20, c[10], c[11]);
            redv2(p + 24, c[12]);
        } else {
            redv2(p,      c[0]);
            redv4(p + 2,  c[1],  c[2]);
            redv4(p + 6,  c[3],  c[4]);
            redv4(p + 10, c[5],  c[6]);
            redv4(p + 14, c[7],  c[8]);
            redv4(p + 18, c[9],  c[10]);
            redv4(p + 22, c[11], c[12]);
        }
    }
}

// ---------------------------------------------------------------------------
// Staged GEMM (D=128). SCAT: red rows into agg via CSR (no output buffer).
// else: store out (+ AGG mean/bias from aggin col-50 count, + RELU).
// Round-13 config: 256 thr, 256 rows/block, 2 rows/thread, 2 blocks/SM.
// A loads use L2 evict-first hints (x is a pure stream; keep agg L2-resident).
// ---------------------------------------------------------------------------
#define WS_F  0
#define BS_F  7168
#define AS0_F 7232
#define AS1_F 16448
#define SMEM_STAGED_BYTES (25664 * 4)

template <bool SCAT, bool AGG, bool RELU>
__global__ void __launch_bounds__(256, 2)
gemm128st(const float* __restrict__ A, const float* __restrict__ W,
          const float* __restrict__ bias, const float* __restrict__ aggin,
          const int* __restrict__ rp, const int* __restrict__ cdst,
          float* __restrict__ out, int nrows)
{
    extern __shared__ float sm[];
    float* Ws = sm + WS_F;
    float* Bs = sm + BS_F;
    const uint32_t smb = smem_u32(sm);

    const int tid = threadIdx.x;
    const int rowbase_blk = blockIdx.x * 256;

    for (int i = tid; i < 7168; i += 256) Ws[i] = 0.f;
    if (tid < 56) Bs[tid] = 0.f;
    __syncthreads();
    for (int i = tid; i < 128 * 50; i += 256) {
        int k = i / 50, c = i % 50;
        Ws[k * 56 + ((c < 26) ? c : c + 2)] = W[i];
    }
    if (AGG && tid < 50) Bs[(tid < 26) ? tid : tid + 2] = bias[tid];

#pragma unroll
    for (int j = 0; j < 8; j++) {
        int idx = j * 256 + tid;
        int row = idx >> 3, f4 = idx & 7;
        int grow = rowbase_blk + row;
        if (grow >= nrows) grow = nrows - 1;
        cp16_ef(smb + (AS0_F + row * 36 + f4 * 4) * 4,
                A + (size_t)grow * 128 + f4 * 4);
    }
    asm volatile("cp.async.commit_group;");
    asm volatile("cp.async.wait_group 0;");
    __syncthreads();

    const int warp = tid >> 5, lane = tid & 31;
    const int sub = lane & 1, rid = lane >> 1;
    const int lrow0 = warp * 32 + rid;
    const int rowbase = rowbase_blk + lrow0;

    ull acc[2][13];
#pragma unroll
    for (int r = 0; r < 2; r++)
#pragma unroll
        for (int j = 0; j < 13; j++) acc[r][j] = 0ULL;

    int cur = 0;
#pragma unroll 1
    for (int p = 0; p < 4; p++) {
        if (p < 3) {
            uint32_t dstb = smb + ((cur ? AS0_F : AS1_F)) * 4;
#pragma unroll
            for (int j = 0; j < 8; j++) {
                int idx = j * 256 + tid;
                int row = idx >> 3, f4 = idx & 7;
                int grow = rowbase_blk + row;
                if (grow >= nrows) grow = nrows - 1;
                cp16_ef(dstb + (row * 36 + f4 * 4) * 4,
                        A + (size_t)grow * 128 + (p + 1) * 32 + f4 * 4);
            }
            asm volatile("cp.async.commit_group;");
        }

        const float* Asc = sm + (cur ? AS1_F : AS0_F);
        const float* a0p = Asc + lrow0 * 36;
        const float* a1p = Asc + (lrow0 + 16) * 36;
        const float* wb = Ws + (p * 32) * 56 + sub * 28;
#pragma unroll
        for (int k0 = 0; k0 < 32; k0 += 4) {
            float4 a0 = *(const float4*)(a0p + k0);
            float4 a1 = *(const float4*)(a1p + k0);
            fma_block(acc, a0.x, a1.x, wb + (k0 + 0) * 56);
            fma_block(acc, a0.y, a1.y, wb + (k0 + 1) * 56);
            fma_block(acc, a0.z, a1.z, wb + (k0 + 2) * 56);
            fma_block(acc, a0.w, a1.w, wb + (k0 + 3) * 56);
        }

        asm volatile("cp.async.wait_group 0;");
        __syncthreads();
        cur ^= 1;
    }

#pragma unroll
    for (int r = 0; r < 2; r++) {
        int row = rowbase + 16 * r;
        if (row >= nrows) continue;
        float2 c[13];
#pragma unroll
        for (int j = 0; j < 13; j++) { F2U cv; cv.u = acc[r][j]; c[j] = cv.f; }
        if (SCAT) {
            scat_row(c, row, sub, rp, cdst, out);
        } else {
            if (AGG) {
                const float* ag = aggin + (size_t)row * PS;
                float ic = 1.f / fmaxf(ag[50], 1.f);
                const float* agh = ag + sub * 26;
                const float* bs = Bs + sub * 28;
#pragma unroll
                for (int j = 0; j < 13; j++) {
                    float2 g = *(const float2*)(agh + 2 * j);
                    c[j].x += g.x * ic + bs[2 * j];
                    c[j].y += g.y * ic + bs[2 * j + 1];
                }
            }
            if (RELU) {
#pragma unroll
                for (int j = 0; j < 13; j++) {
                    c[j].x = fmaxf(c[j].x, 0.f);
                    c[j].y = fmaxf(c[j].y, 0.f);
                }
            }
            float* op = out + (size_t)row * PS + sub * 26;
#pragma unroll
            for (int j = 0; j < 13; j++) *(float2*)(op + 2 * j) = c[j];
        }
    }
}

// ---------------------------------------------------------------------------
// Small-D GEMM (D=52, direct LDG). SCAT: fused scatter + __ldcs streaming A.
// FINAL: dot Wo + relu, 1 float per row.
// ---------------------------------------------------------------------------
template <bool SCAT, bool AGG, bool FINAL>
__global__ void __launch_bounds__(256, 2)
gemm52(const float* __restrict__ A, const float* __restrict__ W,
       const float* __restrict__ bias, const float* __restrict__ aggin,
       const int* __restrict__ rp, const int* __restrict__ cdst,
       float* __restrict__ out, int nrows,
       const float* __restrict__ Wo, const float* __restrict__ bo)
{
    __shared__ float Ws[52 * 56];
    __shared__ float Bs[56];
    __shared__ float Wos[56];

    const int tid = threadIdx.x;
    for (int i = tid; i < 52 * 56; i += 256) Ws[i] = 0.f;
    if (tid < 56) { Bs[tid] = 0.f; Wos[tid] = 0.f; }
    __syncthreads();
    for (int i = tid; i < 50 * 50; i += 256) {
        int k = i / 50, c = i % 50;
        Ws[k * 56 + ((c < 26) ? c : c + 2)] = W[i];
    }
    if (AGG && tid < 50) Bs[(tid < 26) ? tid : tid + 2] = bias[tid];
    if (FINAL && tid < 50) Wos[(tid < 26) ? tid : tid + 2] = Wo[tid];
    __syncthreads();

    const int warp = tid >> 5, lane = tid & 31;
    const int sub = lane & 1, rid = lane >> 1;
    const int rowbase = blockIdx.x * 256 + warp * 32 + rid;

    const float* Ar[2];
#pragma unroll
    for (int r = 0; r < 2; r++) {
        int row = rowbase + 16 * r;
        Ar[r] = A + (size_t)((row < nrows) ? row : 0) * PS;
    }

    ull acc[2][13];
#pragma unroll
    for (int r = 0; r < 2; r++)
#pragma unroll
        for (int j = 0; j < 13; j++) acc[r][j] = 0ULL;

    float4 cur0 = SCAT ? __ldcs((const float4*)Ar[0]) : *(const float4*)(Ar[0]);
    float4 cur1 = SCAT ? __ldcs((const float4*)Ar[1]) : *(const float4*)(Ar[1]);
#pragma unroll 1
    for (int k0 = 0; k0 < 52; k0 += 4) {
        const int kn = (k0 + 4 < 52) ? k0 + 4 : 0;
        float4 nxt0 = SCAT ? __ldcs((const float4*)(Ar[0] + kn)) : *(const float4*)(Ar[0] + kn);
        float4 nxt1 = SCAT ? __ldcs((const float4*)(Ar[1] + kn)) : *(const float4*)(Ar[1] + kn);
        const float* wb = Ws + k0 * 56 + sub * 28;
        fma_block(acc, cur0.x, cur1.x, wb);
        fma_block(acc, cur0.y, cur1.y, wb + 56);
        fma_block(acc, cur0.z, cur1.z, wb + 112);
        fma_block(acc, cur0.w, cur1.w, wb + 168);
        cur0 = nxt0; cur1 = nxt1;
    }

#pragma unroll
    for (int r = 0; r < 2; r++) {
        int row = rowbase + 16 * r;
        if (row >= nrows) continue;
        float2 c[13];
#pragma unroll
        for (int j = 0; j < 13; j++) { F2U cv; cv.u = acc[r][j]; c[j] = cv.f; }
        if (SCAT) {
            scat_row(c, row, sub, rp, cdst, out);
        } else {
            if (AGG) {
                const float* ag = aggin + (size_t)row * PS;
                float ic = 1.f / fmaxf(ag[50], 1.f);
                const float* agh = ag + sub * 26;
                const float* bs = Bs + sub * 28;
#pragma unroll
                for (int j = 0; j < 13; j++) {
                    float2 g = *(const float2*)(agh + 2 * j);
                    c[j].x += g.x * ic + bs[2 * j];
                    c[j].y += g.y * ic + bs[2 * j + 1];
                }
            }
            if (FINAL) {
                const float* ws = Wos + sub * 28;
                float p = 0.f;
#pragma unroll
                for (int j = 0; j < 13; j++)
                    p += c[j].x * ws[2 * j] + c[j].y * ws[2 * j + 1];
                p += __shfl_xor_sync(0xffffffffu, p, 1);
                if (sub == 0) out[row] = fmaxf(p + bo[0], 0.f);
            } else {
                float* op = out + (size_t)row * PS + sub * 26;
#pragma unroll
                for (int j = 0; j < 13; j++) *(float2*)(op + 2 * j) = c[j];
            }
        }
    }
}

// ---------------------------------------------------------------------------
extern "C" void kernel_launch(void* const* d_in, const int* in_sizes, int n_in,
                              void* d_out, int out_size)
{
    const float* x    = (const float*)d_in[0];
    const int*   src0 = (const int*)d_in[2];
    const int*   dst0 = (const int*)d_in[3];
    const int*   src1 = (const int*)d_in[4];
    const int*   dst1 = (const int*)d_in[5];
    const float* Wl1  = (const float*)d_in[8];
    const float* bl1  = (const float*)d_in[9];
    const float* Wr1  = (const float*)d_in[10];
    const float* Wl2  = (const float*)d_in[11];
    const float* bl2  = (const float*)d_in[12];
    const float* Wr2  = (const float*)d_in[13];
    const float* Wo   = (const float*)d_in[14];
    const float* bo   = (const float*)d_in[15];
    float* out = (float*)d_out;

    const int N0 = in_sizes[0] / 128;
    const int E0 = in_sizes[2];
    const int E1 = in_sizes[4];

    float *p_agg1, *p_h, *p_agg2;
    int *p_rp0, *p_rp1, *p_pt0, *p_pt1, *p_cd0, *p_cd1;
    cudaGetSymbolAddress((void**)&p_agg1, g_agg1);
    cudaGetSymbolAddress((void**)&p_h,    g_h);
    cudaGetSymbolAddress((void**)&p_agg2, g_agg2);
    cudaGetSymbolAddress((void**)&p_rp0,  g_rp0);
    cudaGetSymbolAddress((void**)&p_rp1,  g_rp1);
    cudaGetSymbolAddress((void**)&p_pt0,  g_part0);
    cudaGetSymbolAddress((void**)&p_pt1,  g_part1);
    cudaGetSymbolAddress((void**)&p_cd0,  g_cdst0);
    cudaGetSymbolAddress((void**)&p_cd1,  g_cdst1);

    cudaFuncSetAttribute(gemm128st<true, false, false>,
                         cudaFuncAttributeMaxDynamicSharedMemorySize, SMEM_STAGED_BYTES);
    cudaFuncSetAttribute(gemm128st<false, true, true>,
                         cudaFuncAttributeMaxDynamicSharedMemorySize, SMEM_STAGED_BYTES);

    const int n0e = N0 + 1;
    const int n1e = N1C + 1;
    const int nb0 = (n0e + 4095) / 4096;
    const int nb1 = (n1e + 4095) / 4096;

    // 0) zero accumulators + CSR count/fill arrays
    zero_all<<<2048, 256>>>();

    // 1) CSR build (merged launches, both graphs)
    count_edges2<<<(E0 + 255) / 256, 256>>>(src0, E0, src1, E1);
    scan_local2<<<nb0 + nb1, 256>>>(p_rp0, p_pt0, n0e, nb0, p_rp1, p_pt1, n1e);
    scan_part2<<<2, 256>>>(p_pt0, nb0, p_pt1, nb1);
    scan_add2<<<nb0 + nb1, 256>>>(p_rp0, p_pt0, n0e, nb0, p_rp1, p_pt1, n1e);
    fill_csr2<<<(E0 + 255) / 256, 256>>>(src0, dst0, E0, src1, dst1, E1);

    // 2) agg1 <- scatter-sum over edges0 of (x @ Wl1), fused (no y1 buffer)
    gemm128st<true, false, false><<<(N0 + 255) / 256, 256, SMEM_STAGED_BYTES>>>(
        x, Wl1, nullptr, nullptr, p_rp0, p_cd0, p_agg1, N0);

    // 3) h = relu(x[:n1]@Wr1 + bl1 + agg1/cnt)             [n1, 52]
    gemm128st<false, true, true><<<(N1C + 255) / 256, 256, SMEM_STAGED_BYTES>>>(
        x, Wr1, bl1, p_agg1, nullptr, nullptr, p_h, N1C);

    // 4) agg2 <- scatter-sum over edges1 of (h @ Wl2), fused (no y2 buffer)
    gemm52<true, false, false><<<(N1C + 255) / 256, 256>>>(
        p_h, Wl2, nullptr, nullptr, p_rp1, p_cd1, p_agg2, N1C, nullptr, nullptr);

    // 5) out = relu((h[:n2]@Wr2 + bl2 + agg2/cnt) @ Wo + bo)   [n2, 1]
    gemm52<false, true, true><<<(N2C + 255) / 256, 256>>>(
        p_h, Wr2, bl2, p_agg2, nullptr, nullptr, out, N2C, Wo, bo);
}